// round 6
// baseline (speedup 1.0000x reference)
#include <cuda_runtime.h>
#include <cuda_bf16.h>
#include <math_constants.h>

#define BATCH 2048
#define TLEN  4096
#define NSIG  7
#define PRED  64

typedef unsigned long long ull;

__constant__ float c_lrs[NSIG] = {0.01f, 0.08f, 0.1f, 0.15f, 0.2f, 0.25f, 1.0f};

// Scratch (static __device__ — no allocations allowed)
__device__ float g_errs[BATCH * NSIG];
__device__ float g_levels[BATCH * NSIG];
__device__ int   g_bestRow[BATCH];
__device__ int   g_sigIdx[BATCH];

// ---- packed f32x2 helpers (Blackwell; PTX-only path) -----------------------
__device__ __forceinline__ ull pack2(float lo, float hi) {
    ull r; asm("mov.b64 %0, {%1, %2};" : "=l"(r) : "f"(lo), "f"(hi)); return r;
}
__device__ __forceinline__ void unpack2(ull v, float& lo, float& hi) {
    asm("mov.b64 {%0, %1}, %2;" : "=f"(lo), "=f"(hi) : "l"(v));
}
__device__ __forceinline__ ull ffma2(ull a, ull b, ull c) {
    ull d; asm("fma.rn.f32x2 %0, %1, %2, %3;" : "=l"(d) : "l"(a), "l"(b), "l"(c)); return d;
}
__device__ __forceinline__ ull fmul2(ull a, ull b) {
    ull d; asm("mul.rn.f32x2 %0, %1, %2;" : "=l"(d) : "l"(a), "l"(b)); return d;
}

// ---------------------------------------------------------------------------
// K1: innovation-form scan. d_t = a*d_{t-1} + dy_t, d_0 = 0; err = sum d^2;
// level_final = y_last - a*d_last. One block (128 threads) per row, 32
// elems/thread; 6 sigmas in 3 f32x2 pairs, sigma=1 scalar (d = dy).
// ---------------------------------------------------------------------------
__global__ void __launch_bounds__(128) scan_all_kernel(const float* __restrict__ data) {
    constexpr int TPB = 128;
    __shared__ float sLast[TPB];
    __shared__ ull   sWA[4 * 3], sWC[4 * 3];
    __shared__ float sE[NSIG][TPB];

    int r = blockIdx.x;
    int t = threadIdx.x;
    int lane = t & 31;
    int w = t >> 5;

    const float4* row = (const float4*)(data + (size_t)r * TLEN);
    float4 v[8];                           // 32 floats
#pragma unroll
    for (int i = 0; i < 8; i++) v[i] = __ldg(&row[t * 8 + i]);

    sLast[t] = v[7].w;
    __syncthreads();
    float yprev = t ? sLast[t - 1] : v[0].x;   // => dy_0 = 0 for t==0
    float ylast = v[7].w;

    ull A1[3];
    A1[0] = pack2(0.99f, 0.92f);
    A1[1] = pack2(0.90f, 0.85f);
    A1[2] = pack2(0.80f, 0.75f);

    // --- phase1: Horner of dy per pair; dy stored back into v ---------------
    ull H[3] = {0ull, 0ull, 0ull};
    float yp = yprev;
#pragma unroll
    for (int i = 0; i < 8; i++) {
#define P1STEP(REF) { float yy = (REF); float dl = yy - yp; yp = yy; (REF) = dl; \
        ull d2 = pack2(dl, dl);                       \
        H[0] = ffma2(A1[0], H[0], d2);                \
        H[1] = ffma2(A1[1], H[1], d2);                \
        H[2] = ffma2(A1[2], H[2], d2); }
        P1STEP(v[i].x) P1STEP(v[i].y) P1STEP(v[i].z) P1STEP(v[i].w)
#undef P1STEP
    }
    ull A[3], C[3];
#pragma unroll
    for (int p = 0; p < 3; p++) {
        ull a = A1[p];                     // a^32 via 5 packed squarings
        a = fmul2(a, a); a = fmul2(a, a); a = fmul2(a, a);
        a = fmul2(a, a); a = fmul2(a, a);
        A[p] = a;
        C[p] = H[p];                       // no sigma multiply in d-form
    }

    // --- inclusive warp-shuffle scan of transfers ---------------------------
#pragma unroll
    for (int p = 0; p < 3; p++) {
#pragma unroll
        for (int off = 1; off < 32; off <<= 1) {
            ull pa = __shfl_up_sync(0xffffffffu, A[p], off);
            ull pc = __shfl_up_sync(0xffffffffu, C[p], off);
            if (lane >= off) { C[p] = ffma2(A[p], pc, C[p]); A[p] = fmul2(A[p], pa); }
        }
        if (lane == 31) { sWA[w * 3 + p] = A[p]; sWC[w * 3 + p] = C[p]; }
    }
    __syncthreads();

    // entry d for this thread: cross-warp fold (d_init = 0) + in-warp exclusive
    ull Dent[3];
#pragma unroll
    for (int p = 0; p < 3; p++) {
        ull pc = 0ull;
#pragma unroll
        for (int j = 0; j < 3; j++)
            if (j < w) pc = ffma2(sWA[j * 3 + p], pc, sWC[j * 3 + p]);
        ull eA = __shfl_up_sync(0xffffffffu, A[p], 1);
        ull eC = __shfl_up_sync(0xffffffffu, C[p], 1);
        Dent[p] = (lane == 0) ? pc : ffma2(eA, pc, eC);
    }

    // --- phase2: d-recurrence + error accumulation --------------------------
    ull D[3] = {Dent[0], Dent[1], Dent[2]};
    ull E[3] = {0ull, 0ull, 0ull};
    float e6 = 0.0f;
#pragma unroll
    for (int i = 0; i < 8; i++) {
#define P2STEP(REF) { float dl = (REF); ull d2 = pack2(dl, dl);  \
        D[0] = ffma2(A1[0], D[0], d2); E[0] = ffma2(D[0], D[0], E[0]); \
        D[1] = ffma2(A1[1], D[1], d2); E[1] = ffma2(D[1], D[1], E[1]); \
        D[2] = ffma2(A1[2], D[2], d2); E[2] = ffma2(D[2], D[2], E[2]); \
        e6 = fmaf(dl, dl, e6); }
        P2STEP(v[i].x) P2STEP(v[i].y) P2STEP(v[i].z) P2STEP(v[i].w)
#undef P2STEP
    }

    float ev[NSIG];
    unpack2(E[0], ev[0], ev[1]);
    unpack2(E[1], ev[2], ev[3]);
    unpack2(E[2], ev[4], ev[5]);
    ev[6] = e6;
#pragma unroll
    for (int q = 0; q < NSIG; q++) sE[q][t] = ev[q];

    if (t == TPB - 1) {                    // level_final = y_last - a*d_last
        float d0, d1;
        unpack2(D[0], d0, d1);
        g_levels[r * NSIG + 0] = fmaf(-0.99f, d0, ylast);
        g_levels[r * NSIG + 1] = fmaf(-0.92f, d1, ylast);
        unpack2(D[1], d0, d1);
        g_levels[r * NSIG + 2] = fmaf(-0.90f, d0, ylast);
        g_levels[r * NSIG + 3] = fmaf(-0.85f, d1, ylast);
        unpack2(D[2], d0, d1);
        g_levels[r * NSIG + 4] = fmaf(-0.80f, d0, ylast);
        g_levels[r * NSIG + 5] = fmaf(-0.75f, d1, ylast);
        g_levels[r * NSIG + 6] = ylast;    // sigma=1
    }
    __syncthreads();

    if (t < 64) {
#pragma unroll
        for (int q = 0; q < NSIG; q++) sE[q][t] += sE[q][t + 64];
    }
    __syncthreads();
    if (t < 32) {
#pragma unroll
        for (int q = 0; q < NSIG; q++) {
            float x = sE[q][t] + sE[q][t + 32];
#pragma unroll
            for (int off = 16; off > 0; off >>= 1)
                x += __shfl_down_sync(0xffffffffu, x, off);
            if (t == 0) g_errs[r * NSIG + q] = x * (1.0f / (float)TLEN);
        }
    }
}

// ---------------------------------------------------------------------------
// K2: per-row argmin over 7 sigmas (first-min), then strict-< running prefix
// min over rows (prefer-left on ties) via warp-shuffle scan.
// ---------------------------------------------------------------------------
__global__ void pick_kernel() {
    __shared__ float s_min[BATCH];
    __shared__ int   s_idx[BATCH];
    int tid = threadIdx.x;

    for (int b = tid; b < BATCH; b += blockDim.x) {
        const float* e = g_errs + b * NSIG;
        float best = e[0]; int bi = 0;
#pragma unroll
        for (int s = 1; s < NSIG; s++) {
            float v = e[s];
            if (v < best) { best = v; bi = s; }
        }
        s_min[b] = best; s_idx[b] = bi;
    }
    __syncthreads();

    if (tid < 32) {
        int lane = tid;
        float carryV = CUDART_INF_F;
        int   carryR = 0;
        for (int c = 0; c < BATCH / 32; c++) {
            int b = c * 32 + lane;
            float v = s_min[b];
            int   r = b;
#pragma unroll
            for (int off = 1; off < 32; off <<= 1) {
                float pv = __shfl_up_sync(0xffffffffu, v, off);
                int   pr = __shfl_up_sync(0xffffffffu, r, off);
                if (lane >= off && !(v < pv)) { v = pv; r = pr; }
            }
            if (!(v < carryV)) { v = carryV; r = carryR; }
            g_bestRow[b] = r;
            g_sigIdx[b]  = s_idx[r];
            carryV = __shfl_sync(0xffffffffu, v, 31);
            carryR = __shfl_sync(0xffffffffu, r, 31);
        }
    }
}

// ---------------------------------------------------------------------------
// K3 (fused filt+diff+preds): one block per output row b.
// Reconstructs d of source row r = bestRow[b] via scalar d-scan (r-rows are
// ~log B distinct => L2-hot), then out[b][t] = (y_b - y_r) + d_r.
// Threads 0..15 also write the 64-wide broadcast preds row.
// ---------------------------------------------------------------------------
__global__ void __launch_bounds__(128) filtdiff_kernel(const float* __restrict__ data,
                                                       float* __restrict__ out) {
    constexpr int TPB = 128;
    __shared__ float sLast[TPB];
    __shared__ float sWA[4], sWC[4];

    int b = blockIdx.x;
    int t = threadIdx.x;
    int lane = t & 31;
    int w = t >> 5;

    int r = g_bestRow[b];
    float sigma = c_lrs[g_sigIdx[b]];
    float a = 1.0f - sigma;

    const float4* rowr = (const float4*)(data + (size_t)r * TLEN);
    float4 vr[8];
#pragma unroll
    for (int i = 0; i < 8; i++) vr[i] = __ldg(&rowr[t * 8 + i]);

    sLast[t] = vr[7].w;
    __syncthreads();
    float yprev = t ? sLast[t - 1] : vr[0].x;

    // phase1: Horner of dy
    float H = 0.0f, yp = yprev;
#pragma unroll
    for (int i = 0; i < 8; i++) {
        H = fmaf(a, H, vr[i].x - yp);
        H = fmaf(a, H, vr[i].y - vr[i].x);
        H = fmaf(a, H, vr[i].z - vr[i].y);
        H = fmaf(a, H, vr[i].w - vr[i].z);
        yp = vr[i].w;
    }
    float A = a;                           // a^32
    A *= A; A *= A; A *= A; A *= A; A *= A;
    float C = H;

    // warp scan of (A, C)
#pragma unroll
    for (int off = 1; off < 32; off <<= 1) {
        float pa = __shfl_up_sync(0xffffffffu, A, off);
        float pc = __shfl_up_sync(0xffffffffu, C, off);
        if (lane >= off) { C = fmaf(A, pc, C); A *= pa; }
    }
    if (lane == 31) { sWA[w] = A; sWC[w] = C; }
    __syncthreads();

    float dwe = 0.0f;
#pragma unroll
    for (int j = 0; j < 3; j++)
        if (j < w) dwe = fmaf(sWA[j], dwe, sWC[j]);
    float eA = __shfl_up_sync(0xffffffffu, A, 1);
    float eC = __shfl_up_sync(0xffffffffu, C, 1);
    float D = (lane == 0) ? dwe : fmaf(eA, dwe, eC);

    // phase2: d-recurrence + output
    const float4* rowb = (const float4*)(data + (size_t)b * TLEN);
    float4*       orow = (float4*)(out + (size_t)b * TLEN);
    yp = yprev;
#pragma unroll
    for (int i = 0; i < 8; i++) {
        float4 db = __ldg(&rowb[t * 8 + i]);
        float4 o;
        float dl;
        dl = vr[i].x - yp;      D = fmaf(a, D, dl); o.x = (db.x - vr[i].x) + D;
        dl = vr[i].y - vr[i].x; D = fmaf(a, D, dl); o.y = (db.y - vr[i].y) + D;
        dl = vr[i].z - vr[i].y; D = fmaf(a, D, dl); o.z = (db.z - vr[i].z) + D;
        dl = vr[i].w - vr[i].z; D = fmaf(a, D, dl); o.w = (db.w - vr[i].w) + D;
        yp = vr[i].w;
        __stcs(&orow[t * 8 + i], o);
    }

    // preds: 16 float4 per row, broadcast of row b's level at the best sigma
    if (t < PRED / 4) {
        float val = g_levels[b * NSIG + g_sigIdx[b]];
        float4 pv = make_float4(val, val, val, val);
        __stcs((float4*)(out + (size_t)BATCH * TLEN + (size_t)b * PRED) + t, pv);
    }
}

// ---------------------------------------------------------------------------
extern "C" void kernel_launch(void* const* d_in, const int* in_sizes, int n_in,
                              void* d_out, int out_size) {
    const float* data = (const float*)d_in[0];
    float* out = (float*)d_out;

    scan_all_kernel<<<BATCH, 128>>>(data);
    pick_kernel<<<1, 256>>>();
    filtdiff_kernel<<<BATCH, 128>>>(data, out);
}

// round 8
// speedup vs baseline: 1.3725x; 1.3725x over previous
#include <cuda_runtime.h>
#include <cuda_bf16.h>
#include <math_constants.h>

#define BATCH 2048
#define TLEN  4096
#define NSIG  7
#define PRED  64

typedef unsigned long long ull;

__constant__ float c_lrs[NSIG] = {0.01f, 0.08f, 0.1f, 0.15f, 0.2f, 0.25f, 1.0f};

// Scratch (static __device__ — no allocations allowed)
__device__ float g_errs[BATCH * NSIG];
__device__ float g_levels[BATCH * NSIG];
__device__ int   g_bestRow[BATCH];
__device__ int   g_sigIdx[BATCH];
__device__ float g_filt[(size_t)BATCH * TLEN];   // only ~log2(B) rows ever written

// ---- packed f32x2 helpers (Blackwell; PTX-only path) -----------------------
__device__ __forceinline__ ull pack2(float lo, float hi) {
    ull r; asm("mov.b64 %0, {%1, %2};" : "=l"(r) : "f"(lo), "f"(hi)); return r;
}
__device__ __forceinline__ void unpack2(ull v, float& lo, float& hi) {
    asm("mov.b64 {%0, %1}, %2;" : "=f"(lo), "=f"(hi) : "l"(v));
}
__device__ __forceinline__ ull ffma2(ull a, ull b, ull c) {
    ull d; asm("fma.rn.f32x2 %0, %1, %2, %3;" : "=l"(d) : "l"(a), "l"(b), "l"(c)); return d;
}
__device__ __forceinline__ ull fmul2(ull a, ull b) {
    ull d; asm("mul.rn.f32x2 %0, %1, %2;" : "=l"(d) : "l"(a), "l"(b)); return d;
}

// ---------------------------------------------------------------------------
// K1: innovation-form scan, occupancy-shaped: 256 threads/block, 16 elems/
// thread (v[4] -> ~16 fewer regs than the 128x32 shape; scan was measured
// warp-starved at occ=38%, issue=35%).
// d_t = a*d_{t-1} + dy_t, d_0 = 0; err = sum d^2; level = y_last - a*d_last.
// 6 sigmas in 3 f32x2 pairs; sigma=1 scalar (d = dy).
// ---------------------------------------------------------------------------
__global__ void __launch_bounds__(256) scan_all_kernel(const float* __restrict__ data) {
    constexpr int TPB = 256;
    constexpr int NW  = TPB / 32;          // 8 warps
    __shared__ float sLast[TPB];
    __shared__ ull   sWA[NW * 3], sWC[NW * 3];
    __shared__ float sE[NSIG][TPB];

    int r = blockIdx.x;
    int t = threadIdx.x;
    int lane = t & 31;
    int w = t >> 5;

    const float4* row = (const float4*)(data + (size_t)r * TLEN);
    float4 v[4];                           // 16 floats
#pragma unroll
    for (int i = 0; i < 4; i++) v[i] = __ldg(&row[t * 4 + i]);

    sLast[t] = v[3].w;
    __syncthreads();
    float yprev = t ? sLast[t - 1] : v[0].x;   // => dy_0 = 0 for t==0
    float ylast = v[3].w;

    ull A1[3];
    A1[0] = pack2(0.99f, 0.92f);
    A1[1] = pack2(0.90f, 0.85f);
    A1[2] = pack2(0.80f, 0.75f);

    // --- phase1: Horner of dy per pair; dy stored back into v ---------------
    ull H[3] = {0ull, 0ull, 0ull};
    float yp = yprev;
#pragma unroll
    for (int i = 0; i < 4; i++) {
#define P1STEP(REF) { float yy = (REF); float dl = yy - yp; yp = yy; (REF) = dl; \
        ull d2 = pack2(dl, dl);                       \
        H[0] = ffma2(A1[0], H[0], d2);                \
        H[1] = ffma2(A1[1], H[1], d2);                \
        H[2] = ffma2(A1[2], H[2], d2); }
        P1STEP(v[i].x) P1STEP(v[i].y) P1STEP(v[i].z) P1STEP(v[i].w)
#undef P1STEP
    }
    ull A[3], C[3];
#pragma unroll
    for (int p = 0; p < 3; p++) {
        ull a = A1[p];                     // a^16 via 4 packed squarings
        a = fmul2(a, a); a = fmul2(a, a); a = fmul2(a, a); a = fmul2(a, a);
        A[p] = a;
        C[p] = H[p];                       // no sigma multiply in d-form
    }

    // --- inclusive warp-shuffle scan of transfers ---------------------------
#pragma unroll
    for (int p = 0; p < 3; p++) {
#pragma unroll
        for (int off = 1; off < 32; off <<= 1) {
            ull pa = __shfl_up_sync(0xffffffffu, A[p], off);
            ull pc = __shfl_up_sync(0xffffffffu, C[p], off);
            if (lane >= off) { C[p] = ffma2(A[p], pc, C[p]); A[p] = fmul2(A[p], pa); }
        }
        if (lane == 31) { sWA[w * 3 + p] = A[p]; sWC[w * 3 + p] = C[p]; }
    }
    __syncthreads();

    // entry d: cross-warp fold (d_init = 0) + in-warp exclusive
    ull Dent[3];
#pragma unroll
    for (int p = 0; p < 3; p++) {
        ull pc = 0ull;
#pragma unroll
        for (int j = 0; j < NW - 1; j++)
            if (j < w) pc = ffma2(sWA[j * 3 + p], pc, sWC[j * 3 + p]);
        ull eA = __shfl_up_sync(0xffffffffu, A[p], 1);
        ull eC = __shfl_up_sync(0xffffffffu, C[p], 1);
        Dent[p] = (lane == 0) ? pc : ffma2(eA, pc, eC);
    }

    // --- phase2: d-recurrence + error accumulation --------------------------
    ull D[3] = {Dent[0], Dent[1], Dent[2]};
    ull E[3] = {0ull, 0ull, 0ull};
    float e6 = 0.0f;
#pragma unroll
    for (int i = 0; i < 4; i++) {
#define P2STEP(REF) { float dl = (REF); ull d2 = pack2(dl, dl);  \
        D[0] = ffma2(A1[0], D[0], d2); E[0] = ffma2(D[0], D[0], E[0]); \
        D[1] = ffma2(A1[1], D[1], d2); E[1] = ffma2(D[1], D[1], E[1]); \
        D[2] = ffma2(A1[2], D[2], d2); E[2] = ffma2(D[2], D[2], E[2]); \
        e6 = fmaf(dl, dl, e6); }
        P2STEP(v[i].x) P2STEP(v[i].y) P2STEP(v[i].z) P2STEP(v[i].w)
#undef P2STEP
    }

    float ev[NSIG];
    unpack2(E[0], ev[0], ev[1]);
    unpack2(E[1], ev[2], ev[3]);
    unpack2(E[2], ev[4], ev[5]);
    ev[6] = e6;
#pragma unroll
    for (int q = 0; q < NSIG; q++) sE[q][t] = ev[q];

    if (t == TPB - 1) {                    // level_final = y_last - a*d_last
        float d0, d1;
        unpack2(D[0], d0, d1);
        g_levels[r * NSIG + 0] = fmaf(-0.99f, d0, ylast);
        g_levels[r * NSIG + 1] = fmaf(-0.92f, d1, ylast);
        unpack2(D[1], d0, d1);
        g_levels[r * NSIG + 2] = fmaf(-0.90f, d0, ylast);
        g_levels[r * NSIG + 3] = fmaf(-0.85f, d1, ylast);
        unpack2(D[2], d0, d1);
        g_levels[r * NSIG + 4] = fmaf(-0.80f, d0, ylast);
        g_levels[r * NSIG + 5] = fmaf(-0.75f, d1, ylast);
        g_levels[r * NSIG + 6] = ylast;    // sigma=1
    }
    __syncthreads();

    if (t < 128) {
#pragma unroll
        for (int q = 0; q < NSIG; q++) sE[q][t] += sE[q][t + 128];
    }
    __syncthreads();
    if (t < 64) {
#pragma unroll
        for (int q = 0; q < NSIG; q++) sE[q][t] += sE[q][t + 64];
    }
    __syncthreads();
    if (t < 32) {
#pragma unroll
        for (int q = 0; q < NSIG; q++) {
            float x = sE[q][t] + sE[q][t + 32];
#pragma unroll
            for (int off = 16; off > 0; off >>= 1)
                x += __shfl_down_sync(0xffffffffu, x, off);
            if (t == 0) g_errs[r * NSIG + q] = x * (1.0f / (float)TLEN);
        }
    }
}

// ---------------------------------------------------------------------------
// K2: per-row argmin over 7 sigmas (first-min), then strict-< running prefix
// min over rows (prefer-left on ties) via warp-shuffle scan.
// ---------------------------------------------------------------------------
__global__ void pick_kernel() {
    __shared__ float s_min[BATCH];
    __shared__ int   s_idx[BATCH];
    int tid = threadIdx.x;

    for (int b = tid; b < BATCH; b += blockDim.x) {
        const float* e = g_errs + b * NSIG;
        float best = e[0]; int bi = 0;
#pragma unroll
        for (int s = 1; s < NSIG; s++) {
            float v = e[s];
            if (v < best) { best = v; bi = s; }
        }
        s_min[b] = best; s_idx[b] = bi;
    }
    __syncthreads();

    if (tid < 32) {
        int lane = tid;
        float carryV = CUDART_INF_F;
        int   carryR = 0;
        for (int c = 0; c < BATCH / 32; c++) {
            int b = c * 32 + lane;
            float v = s_min[b];
            int   r = b;
#pragma unroll
            for (int off = 1; off < 32; off <<= 1) {
                float pv = __shfl_up_sync(0xffffffffu, v, off);
                int   pr = __shfl_up_sync(0xffffffffu, r, off);
                if (lane >= off && !(v < pv)) { v = pv; r = pr; }
            }
            if (!(v < carryV)) { v = carryV; r = carryR; }
            g_bestRow[b] = r;
            g_sigIdx[b]  = s_idx[r];
            carryV = __shfl_sync(0xffffffffu, v, 31);
            carryR = __shfl_sync(0xffffffffu, r, 31);
        }
    }
}

// ---------------------------------------------------------------------------
// K3a: recompute & store the filtered series only for rows that are ever
// "best" (bestRow[r] == r); chunked scan, 128 threads. filt is PRIOR level.
// (level-form, proven rel_err ~4e-11; only ~log2(B) blocks do work)
// ---------------------------------------------------------------------------
__global__ void __launch_bounds__(128) filt_kernel(const float* __restrict__ data) {
    constexpr int TPB = 128;
    constexpr int EPT = TLEN / TPB;       // 32 elements per thread
    __shared__ float sA[TPB], sC[TPB];
    __shared__ float s_y0;

    int r = blockIdx.x;
    if (g_bestRow[r] != r) return;        // uniform across block
    int t = threadIdx.x;

    float sigma = c_lrs[g_sigIdx[r]];
    float a = 1.0f - sigma;

    const float4* row = (const float4*)(data + (size_t)r * TLEN);
    float4 v[EPT / 4];
#pragma unroll
    for (int i = 0; i < EPT / 4; i++) v[i] = __ldg(&row[t * (EPT / 4) + i]);

    if (t == 0) s_y0 = v[0].x;
    __syncthreads();
    float y0 = s_y0;

    float H = 0.0f;
#pragma unroll
    for (int i = 0; i < EPT / 4; i++) {
        H = fmaf(a, H, v[i].x); H = fmaf(a, H, v[i].y);
        H = fmaf(a, H, v[i].z); H = fmaf(a, H, v[i].w);
    }
    float A = a;                           // a^32 via 5 squarings
    A *= A; A *= A; A *= A; A *= A; A *= A;
    float C = sigma * H;

    sA[t] = A; sC[t] = C;
    __syncthreads();
#pragma unroll
    for (int off = 1; off < TPB; off <<= 1) {
        float pa = 1.0f, pc = 0.0f;
        if (t >= off) { pa = sA[t - off]; pc = sC[t - off]; }
        __syncthreads();
        if (t >= off) { sC[t] = fmaf(sA[t], pc, sC[t]); sA[t] *= pa; }
        __syncthreads();
    }
    float L = (t == 0) ? y0 : fmaf(sA[t - 1], y0, sC[t - 1]);

    float4* out = (float4*)(g_filt + (size_t)r * TLEN) + t * (EPT / 4);
#pragma unroll
    for (int i = 0; i < EPT / 4; i++) {
        float4 y = v[i];
        float4 f;
        f.x = L; L = fmaf(sigma, y.x - L, L);
        f.y = L; L = fmaf(sigma, y.y - L, L);
        f.z = L; L = fmaf(sigma, y.z - L, L);
        f.w = L; L = fmaf(sigma, y.w - L, L);
        out[i] = f;
    }
}

// ---------------------------------------------------------------------------
// K3b: out[b][t] = data[b][t] - filt[bestRow[b]][t]; first 32K threads also
// write the broadcast preds block (fused K4). Pure streaming, max MLP.
// ---------------------------------------------------------------------------
__global__ void __launch_bounds__(256) diff_kernel(const float* __restrict__ data,
                                                   float* __restrict__ out) {
    const int rowq = TLEN / 4;
    int i = blockIdx.x * blockDim.x + threadIdx.x;
    if (i < BATCH * rowq) {
        int b = i / rowq;
        int c = i - b * rowq;
        int r = g_bestRow[b];
        float4 d = __ldcs((const float4*)data + i);
        float4 f = __ldg((const float4*)g_filt + (size_t)r * rowq + c);
        float4 o;
        o.x = d.x - f.x; o.y = d.y - f.y; o.z = d.z - f.z; o.w = d.w - f.w;
        __stcs((float4*)out + i, o);
    }
    if (i < BATCH * (PRED / 4)) {          // preds: 16 float4 per row
        int b = i >> 4;
        float val = g_levels[b * NSIG + g_sigIdx[b]];
        float4 o = make_float4(val, val, val, val);
        __stcs((float4*)out + BATCH * rowq + i, o);
    }
}

// ---------------------------------------------------------------------------
extern "C" void kernel_launch(void* const* d_in, const int* in_sizes, int n_in,
                              void* d_out, int out_size) {
    const float* data = (const float*)d_in[0];
    float* out = (float*)d_out;

    scan_all_kernel<<<BATCH, 256>>>(data);
    pick_kernel<<<1, 256>>>();
    filt_kernel<<<BATCH, 128>>>(data);
    {
        int nq = BATCH * (TLEN / 4);             // float4 count
        diff_kernel<<<(nq + 255) / 256, 256>>>(data, out);
    }
}